// round 4
// baseline (speedup 1.0000x reference)
#include <cuda_runtime.h>
#include <math.h>

#define NATOMS 5000
#define NPAIRS 160000
#define KCH 128
#define FEAT 1152               /* 9 * 128 */
#define MS 0.1767767f           /* MSG_SCALE */
#define ISC 0.2f                /* INIT_SCALE */
#define SQ3 1.7320508075688772f

__device__ float g_feats[NATOMS * FEAT];
__device__ float g_new[NATOMS * FEAT];
__device__ float4 g_rec[NPAIRS * 4];   /* sorted pair records, 64B each */
__device__ int g_cnt[NATOMS];
__device__ int g_off[NATOMS];

__device__ __forceinline__ float siluf(float x) { return x / (1.f + expf(-x)); }

typedef unsigned long long u64;
__device__ __forceinline__ u64 pk2(float lo, float hi) {
    u64 r; asm("mov.b64 %0,{%1,%2};" : "=l"(r) : "f"(lo), "f"(hi)); return r;
}
__device__ __forceinline__ void upk2(float& lo, float& hi, u64 v) {
    asm("mov.b64 {%0,%1},%2;" : "=f"(lo), "=f"(hi) : "l"(v));
}
__device__ __forceinline__ void fma2(u64& d, u64 a, u64 b) {
    asm("fma.rn.f32x2 %0,%1,%2,%0;" : "+l"(d) : "l"(a), "l"(b));
}

/* ---------------- zero pair counters ---------------- */
__global__ void zero_cnt_kernel() {
    const int i = blockIdx.x * blockDim.x + threadIdx.x;
    if (i < NATOMS) g_cnt[i] = 0;
}

/* ---------------- counting sort: hist / scan / scatter+geometry ------------ */
__global__ void hist_kernel(const int* __restrict__ ctr) {
    int p = blockIdx.x * blockDim.x + threadIdx.x;
    if (p < NPAIRS) atomicAdd(&g_cnt[__ldg(ctr + p)], 1);
}

__global__ __launch_bounds__(1024)
void scan_kernel() {
    __shared__ int wsum[32];
    const int t = threadIdx.x;
    const int base = t * 5;
    int c[5]; int s = 0;
#pragma unroll
    for (int i = 0; i < 5; i++) {
        int idx = base + i;
        c[i] = (idx < NATOMS) ? g_cnt[idx] : 0;
        s += c[i];
    }
    const int lane = t & 31, wid = t >> 5;
    int v = s;
#pragma unroll
    for (int o = 1; o < 32; o <<= 1) {
        int u = __shfl_up_sync(0xffffffffu, v, o);
        if (lane >= o) v += u;
    }
    if (lane == 31) wsum[wid] = v;
    __syncthreads();
    if (wid == 0) {
        int w = wsum[lane];
#pragma unroll
        for (int o = 1; o < 32; o <<= 1) {
            int u = __shfl_up_sync(0xffffffffu, w, o);
            if (lane >= o) w += u;
        }
        wsum[lane] = w;
    }
    __syncthreads();
    int excl = v - s + ((wid > 0) ? wsum[wid - 1] : 0);
#pragma unroll
    for (int i = 0; i < 5; i++) {
        int idx = base + i;
        if (idx < NATOMS) { g_off[idx] = excl; excl += c[i]; }
    }
}

__global__ void scatter_kernel(const float* __restrict__ pos, const float* __restrict__ cells,
                               const int* __restrict__ species, const int* __restrict__ shifts,
                               const int* __restrict__ ctr, const int* __restrict__ nbr,
                               const int* __restrict__ spair)
{
    const int p = blockIdx.x * blockDim.x + threadIdx.x;
    if (p >= NPAIRS) return;
    const int c = __ldg(ctr + p);
    const int n = __ldg(nbr + p);
    const int s = __ldg(spair + p);
    const float sx = (float)__ldg(shifts + 3 * p + 0) - 1.f;
    const float sy = (float)__ldg(shifts + 3 * p + 1) - 1.f;
    const float sz = (float)__ldg(shifts + 3 * p + 2) - 1.f;
    const float* M = cells + 9 * s;
    float vx = __ldg(pos + 3 * n + 0) - __ldg(pos + 3 * c + 0) + sx * __ldg(M + 0) + sy * __ldg(M + 3) + sz * __ldg(M + 6);
    float vy = __ldg(pos + 3 * n + 1) - __ldg(pos + 3 * c + 1) + sx * __ldg(M + 1) + sy * __ldg(M + 4) + sz * __ldg(M + 7);
    float vz = __ldg(pos + 3 * n + 2) - __ldg(pos + 3 * c + 2) + sx * __ldg(M + 2) + sy * __ldg(M + 5) + sz * __ldg(M + 8);
    const float dd = vx * vx + vy * vy + vz * vz + 1e-12f;
    const float d = sqrtf(dd);
    const float id = 1.f / d;
    const float fc = (d < 5.f) ? 0.5f * (cosf(0.6283185307179586f * d) + 1.f) : 0.f;
    float in[8];
#pragma unroll
    for (int b = 0; b < 8; b++) {
        float t = d - 0.7142857142857143f * (float)b;
        in[b] = expf(-2.f * t * t) * fc;
    }
    const int dst = atomicAdd(&g_off[c], 1);
    float4* r = g_rec + dst * 4;
    r[0] = make_float4(__int_as_float(c), __int_as_float(n), __int_as_float(__ldg(species + n)), d);
    r[1] = make_float4(vx * id, vy * id, vz * id, 0.f);
    r[2] = make_float4(in[0], in[1], in[2], in[3]);
    r[3] = make_float4(in[4], in[5], in[6], in[7]);
}

/* ---------------- pair message kernels: warp-per-center, no atomics -------- */
template <int PASS>
__global__ __launch_bounds__(128, 4)
void pair_kernel(const float* __restrict__ embed,
                 const float* __restrict__ w1, const float* __restrict__ b1,
                 const float* __restrict__ w2, const float* __restrict__ b2)
{
    __shared__ float w2s[12288];
    __shared__ float w1s[256];
    __shared__ float b1s[32];
    __shared__ float b2s[384];
    {
        float4* d4 = (float4*)w2s;
        const float4* s4 = (const float4*)w2;
        for (int i = threadIdx.x; i < 3072; i += 128) d4[i] = s4[i];
        for (int i = threadIdx.x; i < 256; i += 128) w1s[i] = w1[i];
        if (threadIdx.x < 32) b1s[threadIdx.x] = b1[threadIdx.x];
        for (int i = threadIdx.x; i < 384; i += 128) b2s[i] = b2[i];
    }
    __syncthreads();

    const int lane = threadIdx.x & 31;
    const int wg = (blockIdx.x * 128 + threadIdx.x) >> 5;
    const int NW = (gridDim.x * 128) >> 5;

    for (int c = wg; c < NATOMS; c += NW) {
        const int cnt = g_cnt[c];
        const int s0 = g_off[c] - cnt;   /* scatter left g_off at segment end */
        float acc[36];
#pragma unroll
        for (int i = 0; i < 36; i++) acc[i] = 0.f;

        for (int q = 0; q < cnt; q += 4) {
            const int nv = min(4, cnt - q);
            /* hidden layer per pair */
            float hac[4];
#pragma unroll
            for (int pp = 0; pp < 4; pp++) {
                if (pp < nv) {
                    const float4* r = g_rec + (s0 + q + pp) * 4;
                    const float4 i0 = __ldg(r + 2);
                    const float4 i1 = __ldg(r + 3);
                    float hacc = b1s[lane];
                    hacc += i0.x * w1s[0 * 32 + lane];
                    hacc += i0.y * w1s[1 * 32 + lane];
                    hacc += i0.z * w1s[2 * 32 + lane];
                    hacc += i0.w * w1s[3 * 32 + lane];
                    hacc += i1.x * w1s[4 * 32 + lane];
                    hacc += i1.y * w1s[5 * 32 + lane];
                    hacc += i1.z * w1s[6 * 32 + lane];
                    hacc += i1.w * w1s[7 * 32 + lane];
                    hac[pp] = siluf(hacc);
                } else hac[pp] = 0.f;
            }

            /* layer-2 GEMM: packed f32x2 */
            u64 Ra[12], Rb[12];
#pragma unroll
            for (int t = 0; t < 12; t++) {
                const float bv = b2s[lane + 32 * t];
                Ra[t] = pk2(bv, bv);
                Rb[t] = Ra[t];
            }
#pragma unroll 2
            for (int b = 0; b < 32; b++) {
                const float h0 = __shfl_sync(0xffffffffu, hac[0], b);
                const float h1 = __shfl_sync(0xffffffffu, hac[1], b);
                const float h2 = __shfl_sync(0xffffffffu, hac[2], b);
                const float h3 = __shfl_sync(0xffffffffu, hac[3], b);
                const u64 hb01 = pk2(h0, h1);
                const u64 hb23 = pk2(h2, h3);
                const float* wrow = w2s + b * 384 + lane;
#pragma unroll
                for (int t = 0; t < 12; t++) {
                    const float w = wrow[32 * t];
                    const u64 wv = pk2(w, w);
                    fma2(Ra[t], wv, hb01);
                    fma2(Rb[t], wv, hb23);
                }
            }

            /* epilogue: accumulate messages into registers */
#pragma unroll
            for (int pp = 0; pp < 4; pp++) {
                if (pp < nv) {
                    const float4* r = g_rec + (s0 + q + pp) * 4;
                    const float4 a0 = __ldg(r + 0);
                    const float4 uu = __ldg(r + 1);
                    const int n = __float_as_int(a0.y);
                    const int sp = __float_as_int(a0.z);
                    const float x = uu.x, y = uu.y, z = uu.z;
                    float R[12];
#pragma unroll
                    for (int t = 0; t < 12; t++) {
                        float lo, hi; upk2(lo, hi, (pp < 2) ? Ra[t] : Rb[t]);
                        R[t] = (pp & 1) ? hi : lo;
                    }
                    const float sh0 = ISC;
                    const float sh1 = ISC * y, sh2 = ISC * z, sh3 = ISC * x;
                    const float sh4 = ISC * SQ3 * x * y;
                    const float sh5 = ISC * SQ3 * y * z;
                    const float sh6 = ISC * 0.5f * (3.f * z * z - 1.f);
                    const float sh7 = ISC * SQ3 * x * z;
                    const float sh8 = ISC * 0.5f * SQ3 * (x * x - y * y);
                    if (PASS == 1) {
                        const float* em = embed + sp * KCH;
#pragma unroll
                        for (int t = 0; t < 4; t++) {
                            const int k = lane + 32 * t;
                            const float e = __ldg(em + k) * MS;
                            const float r0 = R[t] * e, r1 = R[4 + t] * e, r2 = R[8 + t] * e;
                            acc[0 * 4 + t] += sh0 * r0;
                            acc[1 * 4 + t] += sh1 * r1;
                            acc[2 * 4 + t] += sh2 * r1;
                            acc[3 * 4 + t] += sh3 * r1;
                            acc[4 * 4 + t] += sh4 * r2;
                            acc[5 * 4 + t] += sh5 * r2;
                            acc[6 * 4 + t] += sh6 * r2;
                            acc[7 * 4 + t] += sh7 * r2;
                            acc[8 * 4 + t] += sh8 * r2;
                        }
                    } else {
                        const float* gn = g_feats + n * FEAT;
#pragma unroll
                        for (int t = 0; t < 4; t++) {
                            const int k = lane + 32 * t;
                            const float r0 = R[t] * MS, r1 = R[4 + t] * MS, r2 = R[8 + t] * MS;
                            const float inv = __ldg(gn + k);
                            const float u1 = r1 * inv, u2 = r2 * inv;
                            acc[0 * 4 + t] += sh0 * r0 * inv + r0 * inv;
                            acc[1 * 4 + t] += sh1 * u1 + r0 * __ldg(gn + 1 * KCH + k);
                            acc[2 * 4 + t] += sh2 * u1 + r0 * __ldg(gn + 2 * KCH + k);
                            acc[3 * 4 + t] += sh3 * u1 + r0 * __ldg(gn + 3 * KCH + k);
                            acc[4 * 4 + t] += sh4 * u2 + r0 * __ldg(gn + 4 * KCH + k);
                            acc[5 * 4 + t] += sh5 * u2 + r0 * __ldg(gn + 5 * KCH + k);
                            acc[6 * 4 + t] += sh6 * u2 + r0 * __ldg(gn + 6 * KCH + k);
                            acc[7 * 4 + t] += sh7 * u2 + r0 * __ldg(gn + 7 * KCH + k);
                            acc[8 * 4 + t] += sh8 * u2 + r0 * __ldg(gn + 8 * KCH + k);
                        }
                    }
                }
            }
        }

        /* single write-out per center — no atomics */
        if (PASS == 1) {
            float* fb = g_feats + c * FEAT;
#pragma unroll
            for (int comp = 0; comp < 9; comp++)
#pragma unroll
                for (int t = 0; t < 4; t++)
                    fb[comp * KCH + lane + 32 * t] = acc[comp * 4 + t];
        } else {
            float* fb = g_new + c * FEAT;
#pragma unroll
            for (int comp = 0; comp < 9; comp++)
#pragma unroll
                for (int t = 0; t < 4; t++) {
                    const int idx = comp * KCH + lane + 32 * t;
                    fb[idx] += acc[comp * 4 + t];
                }
        }
    }
}

/* ---------------- CG tensor-square iterate (per atom, per k) ---------------- */
template <int BUF>
__global__ __launch_bounds__(128)
void cg_kernel(const float* __restrict__ mix, const float* __restrict__ U2g)
{
    __shared__ float U[81];
    const int k = threadIdx.x;
    if (k < 81) U[k] = U2g[k];
    __syncthreads();
    float* base = ((BUF == 0) ? g_feats : g_new) + blockIdx.x * FEAT + k;
    float* dup  = g_new + blockIdx.x * FEAT + k;

    {
        const float f0 = base[0];
        const float v = f0 + __ldg(mix + k) * f0 * f0;
        base[0] = v;
        if (BUF == 0) dup[0] = v;
    }
    {
        float f1[3];
#pragma unroll
        for (int j = 0; j < 3; j++) f1[j] = base[(1 + j) * KCH];
        float Mv[9];
#pragma unroll
        for (int q = 0; q < 9; q++)
            Mv[q] = U[9 + q] * f1[0] + U[18 + q] * f1[1] + U[27 + q] * f1[2];
        float Cm[9];
#pragma unroll
        for (int i = 0; i < 3; i++)
#pragma unroll
            for (int j = 0; j < 3; j++)
                Cm[3 * i + j] = Mv[3 * i] * Mv[j] + Mv[3 * i + 1] * Mv[3 + j] + Mv[3 * i + 2] * Mv[6 + j];
        const float m1 = __ldg(mix + KCH + k);
        float B[9];
#pragma unroll
        for (int q = 0; q < 9; q++) B[q] = Mv[q] + m1 * Cm[q];
#pragma unroll
        for (int j = 0; j < 3; j++) {
            float o = 0.f;
#pragma unroll
            for (int q = 0; q < 9; q++) o += U[(1 + j) * 9 + q] * B[q];
            base[(1 + j) * KCH] = o;
            if (BUF == 0) dup[(1 + j) * KCH] = o;
        }
    }
    {
        float f2[5];
#pragma unroll
        for (int j = 0; j < 5; j++) f2[j] = base[(4 + j) * KCH];
        float Mv[9];
#pragma unroll
        for (int q = 0; q < 9; q++)
            Mv[q] = U[36 + q] * f2[0] + U[45 + q] * f2[1] + U[54 + q] * f2[2] + U[63 + q] * f2[3] + U[72 + q] * f2[4];
        float Cm[9];
#pragma unroll
        for (int i = 0; i < 3; i++)
#pragma unroll
            for (int j = 0; j < 3; j++)
                Cm[3 * i + j] = Mv[3 * i] * Mv[j] + Mv[3 * i + 1] * Mv[3 + j] + Mv[3 * i + 2] * Mv[6 + j];
        const float m2 = __ldg(mix + 2 * KCH + k);
        float B[9];
#pragma unroll
        for (int q = 0; q < 9; q++) B[q] = Mv[q] + m2 * Cm[q];
#pragma unroll
        for (int j = 0; j < 5; j++) {
            float o = 0.f;
#pragma unroll
            for (int q = 0; q < 9; q++) o += U[(4 + j) * 9 + q] * B[q];
            base[(4 + j) * KCH] = o;
            if (BUF == 0) dup[(4 + j) * KCH] = o;
        }
    }
}

/* ---------------- head MLP: 20 atoms per block ---------------- */
#define APB 20
__global__ __launch_bounds__(128)
void head_kernel(const float* __restrict__ hw1, const float* __restrict__ hb1,
                 const float* __restrict__ hw2, const float* __restrict__ hb2,
                 const float* __restrict__ lw, const float* __restrict__ lb,
                 float* __restrict__ out)
{
    __shared__ float hs[APB][132];
    const int a0 = blockIdx.x * APB;
    const int j = threadIdx.x;

    for (int i = 0; i < APB; i++) hs[i][j] = g_new[(a0 + i) * FEAT + j];
    __syncthreads();

    float acc[APB];
    {
        const float b = __ldg(hb1 + j);
#pragma unroll
        for (int i = 0; i < APB; i++) acc[i] = b;
    }
    for (int kk = 0; kk < 128; kk++) {
        const float w = __ldg(hw1 + kk * 128 + j);
#pragma unroll
        for (int i = 0; i < APB; i++) acc[i] += hs[i][kk] * w;
    }
    __syncthreads();
#pragma unroll
    for (int i = 0; i < APB; i++) hs[i][j] = siluf(acc[i]);
    __syncthreads();
    {
        const float b = __ldg(hb2 + j);
#pragma unroll
        for (int i = 0; i < APB; i++) acc[i] = b;
    }
    for (int kk = 0; kk < 128; kk++) {
        const float w = __ldg(hw2 + kk * 128 + j);
#pragma unroll
        for (int i = 0; i < APB; i++) acc[i] += hs[i][kk] * w;
    }
    __syncthreads();
    {
        const float lwj = __ldg(lw + j);
#pragma unroll
        for (int i = 0; i < APB; i++) hs[i][j] = siluf(acc[i]) * lwj;
    }
    __syncthreads();
    if (j < APB) {
        float s = __ldg(lb);
        for (int q = 0; q < 128; q++) s += hs[j][q];
        out[a0 + j] = s;
    }
}

extern "C" void kernel_launch(void* const* d_in, const int* in_sizes, int n_in,
                              void* d_out, int out_size)
{
    const float* pos     = (const float*)d_in[0];
    const float* cells   = (const float*)d_in[1];
    const int*   species = (const int*)d_in[2];
    const int*   shifts  = (const int*)d_in[3];
    const int*   ctr     = (const int*)d_in[4];
    const int*   nbr     = (const int*)d_in[5];
    const int*   spair   = (const int*)d_in[6];
    const float* embed   = (const float*)d_in[7];
    const float* rw1 = (const float*)d_in[8];
    const float* rb1 = (const float*)d_in[9];
    const float* rw2 = (const float*)d_in[10];
    const float* rb2 = (const float*)d_in[11];
    const float* ew1 = (const float*)d_in[12];
    const float* eb1 = (const float*)d_in[13];
    const float* ew2 = (const float*)d_in[14];
    const float* eb2 = (const float*)d_in[15];
    const float* mixa  = (const float*)d_in[16];
    const float* emixa = (const float*)d_in[17];
    const float* hw1 = (const float*)d_in[18];
    const float* hb1 = (const float*)d_in[19];
    const float* hw2 = (const float*)d_in[20];
    const float* hb2 = (const float*)d_in[21];
    const float* lw  = (const float*)d_in[22];
    const float* lb  = (const float*)d_in[23];
    const float* U2  = (const float*)d_in[24];
    float* out = (float*)d_out;

    zero_cnt_kernel<<<20, 256>>>();
    hist_kernel<<<(NPAIRS + 255) / 256, 256>>>(ctr);
    scan_kernel<<<1, 1024>>>();
    scatter_kernel<<<(NPAIRS + 255) / 256, 256>>>(pos, cells, species, shifts, ctr, nbr, spair);
    pair_kernel<1><<<592, 128>>>(embed, rw1, rb1, rw2, rb2);
    cg_kernel<0><<<NATOMS, 128>>>(mixa, U2);
    pair_kernel<2><<<592, 128>>>(embed, ew1, eb1, ew2, eb2);
    cg_kernel<1><<<NATOMS, 128>>>(emixa, U2);
    head_kernel<<<NATOMS / APB, 128>>>(hw1, hb1, hw2, hb2, lw, lb, out);
}

// round 5
// speedup vs baseline: 1.1691x; 1.1691x over previous
#include <cuda_runtime.h>
#include <math.h>

#define NATOMS 5000
#define NPAIRS 160000
#define KCH 128
#define FEAT 1152               /* 9 * 128 */
#define MS 0.1767767f           /* MSG_SCALE */
#define ISC 0.2f                /* INIT_SCALE */
#define SQ3 1.7320508075688772f

#define PAIR_BLOCKS 444         /* 148 SMs * 3 blocks, one wave */
#define PAIR_WARPS (PAIR_BLOCKS * 4)
#define PPW ((NPAIRS + PAIR_WARPS - 1) / PAIR_WARPS)   /* 91 pairs per warp */

__device__ float g_feats[NATOMS * FEAT];
__device__ float g_new[NATOMS * FEAT];
__device__ float4 g_rec[NPAIRS * 4];   /* sorted pair records, 64B each */
__device__ int g_cnt[NATOMS];
__device__ int g_off[NATOMS];

__device__ __forceinline__ float siluf(float x) { return x / (1.f + expf(-x)); }

typedef unsigned long long u64;
__device__ __forceinline__ u64 pk2(float lo, float hi) {
    u64 r; asm("mov.b64 %0,{%1,%2};" : "=l"(r) : "f"(lo), "f"(hi)); return r;
}
__device__ __forceinline__ void upk2(float& lo, float& hi, u64 v) {
    asm("mov.b64 {%0,%1},%2;" : "=f"(lo), "=f"(hi) : "l"(v));
}
__device__ __forceinline__ void fma2(u64& d, u64 a, u64 b) {
    asm("fma.rn.f32x2 %0,%1,%2,%0;" : "+l"(d) : "l"(a), "l"(b));
}

/* ---------------- zero feats + counters ---------------- */
__global__ void zero_kernel() {
    float4* p = (float4*)g_feats;
    const int n = NATOMS * FEAT / 4;
    const int tid = blockIdx.x * blockDim.x + threadIdx.x;
    for (int i = tid; i < n; i += gridDim.x * blockDim.x)
        p[i] = make_float4(0.f, 0.f, 0.f, 0.f);
    if (tid < NATOMS) g_cnt[tid] = 0;
}

/* ---------------- counting sort: hist / scan / scatter+geometry ------------ */
__global__ void hist_kernel(const int* __restrict__ ctr) {
    int p = blockIdx.x * blockDim.x + threadIdx.x;
    if (p < NPAIRS) atomicAdd(&g_cnt[__ldg(ctr + p)], 1);
}

__global__ __launch_bounds__(1024)
void scan_kernel() {
    __shared__ int wsum[32];
    const int t = threadIdx.x;
    const int base = t * 5;
    int c[5]; int s = 0;
#pragma unroll
    for (int i = 0; i < 5; i++) {
        int idx = base + i;
        c[i] = (idx < NATOMS) ? g_cnt[idx] : 0;
        s += c[i];
    }
    const int lane = t & 31, wid = t >> 5;
    int v = s;
#pragma unroll
    for (int o = 1; o < 32; o <<= 1) {
        int u = __shfl_up_sync(0xffffffffu, v, o);
        if (lane >= o) v += u;
    }
    if (lane == 31) wsum[wid] = v;
    __syncthreads();
    if (wid == 0) {
        int w = wsum[lane];
#pragma unroll
        for (int o = 1; o < 32; o <<= 1) {
            int u = __shfl_up_sync(0xffffffffu, w, o);
            if (lane >= o) w += u;
        }
        wsum[lane] = w;
    }
    __syncthreads();
    int excl = v - s + ((wid > 0) ? wsum[wid - 1] : 0);
#pragma unroll
    for (int i = 0; i < 5; i++) {
        int idx = base + i;
        if (idx < NATOMS) { g_off[idx] = excl; excl += c[i]; }
    }
}

__global__ void scatter_kernel(const float* __restrict__ pos, const float* __restrict__ cells,
                               const int* __restrict__ species, const int* __restrict__ shifts,
                               const int* __restrict__ ctr, const int* __restrict__ nbr,
                               const int* __restrict__ spair)
{
    const int p = blockIdx.x * blockDim.x + threadIdx.x;
    if (p >= NPAIRS) return;
    const int c = __ldg(ctr + p);
    const int n = __ldg(nbr + p);
    const int s = __ldg(spair + p);
    const float sx = (float)__ldg(shifts + 3 * p + 0) - 1.f;
    const float sy = (float)__ldg(shifts + 3 * p + 1) - 1.f;
    const float sz = (float)__ldg(shifts + 3 * p + 2) - 1.f;
    const float* M = cells + 9 * s;
    float vx = __ldg(pos + 3 * n + 0) - __ldg(pos + 3 * c + 0) + sx * __ldg(M + 0) + sy * __ldg(M + 3) + sz * __ldg(M + 6);
    float vy = __ldg(pos + 3 * n + 1) - __ldg(pos + 3 * c + 1) + sx * __ldg(M + 1) + sy * __ldg(M + 4) + sz * __ldg(M + 7);
    float vz = __ldg(pos + 3 * n + 2) - __ldg(pos + 3 * c + 2) + sx * __ldg(M + 2) + sy * __ldg(M + 5) + sz * __ldg(M + 8);
    const float dd = vx * vx + vy * vy + vz * vz + 1e-12f;
    const float d = sqrtf(dd);
    const float id = 1.f / d;
    const float fc = (d < 5.f) ? 0.5f * (cosf(0.6283185307179586f * d) + 1.f) : 0.f;
    float in[8];
#pragma unroll
    for (int b = 0; b < 8; b++) {
        float t = d - 0.7142857142857143f * (float)b;
        in[b] = expf(-2.f * t * t) * fc;
    }
    const int dst = atomicAdd(&g_off[c], 1);
    float4* r = g_rec + dst * 4;
    r[0] = make_float4(__int_as_float(c), __int_as_float(n), __int_as_float(__ldg(species + n)), d);
    r[1] = make_float4(vx * id, vy * id, vz * id, 0.f);
    r[2] = make_float4(in[0], in[1], in[2], in[3]);
    r[3] = make_float4(in[4], in[5], in[6], in[7]);
}

/* ---------------- pair kernels: balanced pair ranges + segment-flush ------- */
template <int PASS>
__global__ __launch_bounds__(128, 3)
void pair_kernel(const float* __restrict__ embed,
                 const float* __restrict__ w1, const float* __restrict__ b1,
                 const float* __restrict__ w2, const float* __restrict__ b2)
{
    __shared__ float w2s[12288];
    __shared__ float w1s[256];
    __shared__ float b1s[32];
    __shared__ float b2s[384];
    {
        float4* d4 = (float4*)w2s;
        const float4* s4 = (const float4*)w2;
        for (int i = threadIdx.x; i < 3072; i += 128) d4[i] = s4[i];
        for (int i = threadIdx.x; i < 256; i += 128) w1s[i] = w1[i];
        if (threadIdx.x < 32) b1s[threadIdx.x] = b1[threadIdx.x];
        for (int i = threadIdx.x; i < 384; i += 128) b2s[i] = b2[i];
    }
    __syncthreads();

    const int lane = threadIdx.x & 31;
    const int w = (blockIdx.x * 128 + threadIdx.x) >> 5;
    const int p0 = w * PPW;
    const int p1 = min(p0 + PPW, NPAIRS);
    if (p0 >= NPAIRS) return;

    float acc[36];
    int cur_c = -1;

#define FLUSH()                                                                 \
    do {                                                                        \
        float* fb = ((PASS == 1) ? g_feats : g_new) + cur_c * FEAT;             \
        _Pragma("unroll")                                                       \
        for (int comp = 0; comp < 9; comp++)                                    \
            _Pragma("unroll")                                                   \
            for (int t = 0; t < 4; t++)                                         \
                atomicAdd(fb + comp * KCH + lane + 32 * t, acc[comp * 4 + t]);  \
    } while (0)

    for (int q = p0; q < p1; q += 4) {
        const int nv = min(4, p1 - q);
        /* hidden layer per pair */
        float hac[4];
#pragma unroll
        for (int pp = 0; pp < 4; pp++) {
            if (pp < nv) {
                const float4* r = g_rec + (q + pp) * 4;
                const float4 i0 = __ldg(r + 2);
                const float4 i1 = __ldg(r + 3);
                float hacc = b1s[lane];
                hacc += i0.x * w1s[0 * 32 + lane];
                hacc += i0.y * w1s[1 * 32 + lane];
                hacc += i0.z * w1s[2 * 32 + lane];
                hacc += i0.w * w1s[3 * 32 + lane];
                hacc += i1.x * w1s[4 * 32 + lane];
                hacc += i1.y * w1s[5 * 32 + lane];
                hacc += i1.z * w1s[6 * 32 + lane];
                hacc += i1.w * w1s[7 * 32 + lane];
                hac[pp] = siluf(hacc);
            } else hac[pp] = 0.f;
        }

        /* layer-2 GEMM: packed f32x2, Ra = pairs(0,1), Rb = pairs(2,3) */
        u64 Ra[12], Rb[12];
#pragma unroll
        for (int t = 0; t < 12; t++) {
            const float bv = b2s[lane + 32 * t];
            Ra[t] = pk2(bv, bv);
            Rb[t] = Ra[t];
        }
#pragma unroll 2
        for (int b = 0; b < 32; b++) {
            const float h0 = __shfl_sync(0xffffffffu, hac[0], b);
            const float h1 = __shfl_sync(0xffffffffu, hac[1], b);
            const float h2 = __shfl_sync(0xffffffffu, hac[2], b);
            const float h3 = __shfl_sync(0xffffffffu, hac[3], b);
            const u64 hb01 = pk2(h0, h1);
            const u64 hb23 = pk2(h2, h3);
            const float* wrow = w2s + b * 384 + lane;
#pragma unroll
            for (int t = 0; t < 12; t++) {
                const float wv0 = wrow[32 * t];
                const u64 wv = pk2(wv0, wv0);
                fma2(Ra[t], wv, hb01);
                fma2(Rb[t], wv, hb23);
            }
        }

        /* epilogue: accumulate into per-center register accumulator */
#pragma unroll
        for (int pp = 0; pp < 4; pp++) {
            if (pp < nv) {
                const float4* r = g_rec + (q + pp) * 4;
                const float4 a0 = __ldg(r + 0);
                const float4 uu = __ldg(r + 1);
                const int c = __float_as_int(a0.x);
                const int n = __float_as_int(a0.y);
                const int sp = __float_as_int(a0.z);
                const float x = uu.x, y = uu.y, z = uu.z;

                if (c != cur_c) {
                    if (cur_c >= 0) FLUSH();
                    cur_c = c;
#pragma unroll
                    for (int i = 0; i < 36; i++) acc[i] = 0.f;
                }

                float R[12];
#pragma unroll
                for (int t = 0; t < 12; t++) {
                    float lo, hi; upk2(lo, hi, (pp < 2) ? Ra[t] : Rb[t]);
                    R[t] = (pp & 1) ? hi : lo;
                }
                const float sh0 = ISC;
                const float sh1 = ISC * y, sh2 = ISC * z, sh3 = ISC * x;
                const float sh4 = ISC * SQ3 * x * y;
                const float sh5 = ISC * SQ3 * y * z;
                const float sh6 = ISC * 0.5f * (3.f * z * z - 1.f);
                const float sh7 = ISC * SQ3 * x * z;
                const float sh8 = ISC * 0.5f * SQ3 * (x * x - y * y);

                if (PASS == 1) {
                    const float* em = embed + sp * KCH;
#pragma unroll
                    for (int t = 0; t < 4; t++) {
                        const int k = lane + 32 * t;
                        const float e = __ldg(em + k) * MS;
                        const float r0 = R[t] * e, r1 = R[4 + t] * e, r2 = R[8 + t] * e;
                        acc[0 * 4 + t] += sh0 * r0;
                        acc[1 * 4 + t] += sh1 * r1;
                        acc[2 * 4 + t] += sh2 * r1;
                        acc[3 * 4 + t] += sh3 * r1;
                        acc[4 * 4 + t] += sh4 * r2;
                        acc[5 * 4 + t] += sh5 * r2;
                        acc[6 * 4 + t] += sh6 * r2;
                        acc[7 * 4 + t] += sh7 * r2;
                        acc[8 * 4 + t] += sh8 * r2;
                    }
                } else {
                    const float* gn = g_feats + n * FEAT;
#pragma unroll
                    for (int t = 0; t < 4; t++) {
                        const int k = lane + 32 * t;
                        const float r0 = R[t] * MS, r1 = R[4 + t] * MS, r2 = R[8 + t] * MS;
                        const float inv = __ldg(gn + k);
                        const float u1 = r1 * inv, u2 = r2 * inv;
                        acc[0 * 4 + t] += sh0 * r0 * inv + r0 * inv;
                        acc[1 * 4 + t] += sh1 * u1 + r0 * __ldg(gn + 1 * KCH + k);
                        acc[2 * 4 + t] += sh2 * u1 + r0 * __ldg(gn + 2 * KCH + k);
                        acc[3 * 4 + t] += sh3 * u1 + r0 * __ldg(gn + 3 * KCH + k);
                        acc[4 * 4 + t] += sh4 * u2 + r0 * __ldg(gn + 4 * KCH + k);
                        acc[5 * 4 + t] += sh5 * u2 + r0 * __ldg(gn + 5 * KCH + k);
                        acc[6 * 4 + t] += sh6 * u2 + r0 * __ldg(gn + 6 * KCH + k);
                        acc[7 * 4 + t] += sh7 * u2 + r0 * __ldg(gn + 7 * KCH + k);
                        acc[8 * 4 + t] += sh8 * u2 + r0 * __ldg(gn + 8 * KCH + k);
                    }
                }
            }
        }
    }
    if (cur_c >= 0) FLUSH();
#undef FLUSH
}

/* ---------------- CG tensor-square iterate (per atom, per k) ---------------- */
template <int BUF>
__global__ __launch_bounds__(128)
void cg_kernel(const float* __restrict__ mix, const float* __restrict__ U2g)
{
    __shared__ float U[81];
    const int k = threadIdx.x;
    if (k < 81) U[k] = U2g[k];
    __syncthreads();
    float* base = ((BUF == 0) ? g_feats : g_new) + blockIdx.x * FEAT + k;
    float* dup  = g_new + blockIdx.x * FEAT + k;

    {
        const float f0 = base[0];
        const float v = f0 + __ldg(mix + k) * f0 * f0;
        base[0] = v;
        if (BUF == 0) dup[0] = v;
    }
    {
        float f1[3];
#pragma unroll
        for (int j = 0; j < 3; j++) f1[j] = base[(1 + j) * KCH];
        float Mv[9];
#pragma unroll
        for (int q = 0; q < 9; q++)
            Mv[q] = U[9 + q] * f1[0] + U[18 + q] * f1[1] + U[27 + q] * f1[2];
        float Cm[9];
#pragma unroll
        for (int i = 0; i < 3; i++)
#pragma unroll
            for (int j = 0; j < 3; j++)
                Cm[3 * i + j] = Mv[3 * i] * Mv[j] + Mv[3 * i + 1] * Mv[3 + j] + Mv[3 * i + 2] * Mv[6 + j];
        const float m1 = __ldg(mix + KCH + k);
        float B[9];
#pragma unroll
        for (int q = 0; q < 9; q++) B[q] = Mv[q] + m1 * Cm[q];
#pragma unroll
        for (int j = 0; j < 3; j++) {
            float o = 0.f;
#pragma unroll
            for (int q = 0; q < 9; q++) o += U[(1 + j) * 9 + q] * B[q];
            base[(1 + j) * KCH] = o;
            if (BUF == 0) dup[(1 + j) * KCH] = o;
        }
    }
    {
        float f2[5];
#pragma unroll
        for (int j = 0; j < 5; j++) f2[j] = base[(4 + j) * KCH];
        float Mv[9];
#pragma unroll
        for (int q = 0; q < 9; q++)
            Mv[q] = U[36 + q] * f2[0] + U[45 + q] * f2[1] + U[54 + q] * f2[2] + U[63 + q] * f2[3] + U[72 + q] * f2[4];
        float Cm[9];
#pragma unroll
        for (int i = 0; i < 3; i++)
#pragma unroll
            for (int j = 0; j < 3; j++)
                Cm[3 * i + j] = Mv[3 * i] * Mv[j] + Mv[3 * i + 1] * Mv[3 + j] + Mv[3 * i + 2] * Mv[6 + j];
        const float m2 = __ldg(mix + 2 * KCH + k);
        float B[9];
#pragma unroll
        for (int q = 0; q < 9; q++) B[q] = Mv[q] + m2 * Cm[q];
#pragma unroll
        for (int j = 0; j < 5; j++) {
            float o = 0.f;
#pragma unroll
            for (int q = 0; q < 9; q++) o += U[(4 + j) * 9 + q] * B[q];
            base[(4 + j) * KCH] = o;
            if (BUF == 0) dup[(4 + j) * KCH] = o;
        }
    }
}

/* ---------------- head MLP: 20 atoms per block ---------------- */
#define APB 20
__global__ __launch_bounds__(128)
void head_kernel(const float* __restrict__ hw1, const float* __restrict__ hb1,
                 const float* __restrict__ hw2, const float* __restrict__ hb2,
                 const float* __restrict__ lw, const float* __restrict__ lb,
                 float* __restrict__ out)
{
    __shared__ float hs[APB][132];
    const int a0 = blockIdx.x * APB;
    const int j = threadIdx.x;

    for (int i = 0; i < APB; i++) hs[i][j] = g_new[(a0 + i) * FEAT + j];
    __syncthreads();

    float acc[APB];
    {
        const float b = __ldg(hb1 + j);
#pragma unroll
        for (int i = 0; i < APB; i++) acc[i] = b;
    }
    for (int kk = 0; kk < 128; kk++) {
        const float w = __ldg(hw1 + kk * 128 + j);
#pragma unroll
        for (int i = 0; i < APB; i++) acc[i] += hs[i][kk] * w;
    }
    __syncthreads();
#pragma unroll
    for (int i = 0; i < APB; i++) hs[i][j] = siluf(acc[i]);
    __syncthreads();
    {
        const float b = __ldg(hb2 + j);
#pragma unroll
        for (int i = 0; i < APB; i++) acc[i] = b;
    }
    for (int kk = 0; kk < 128; kk++) {
        const float w = __ldg(hw2 + kk * 128 + j);
#pragma unroll
        for (int i = 0; i < APB; i++) acc[i] += hs[i][kk] * w;
    }
    __syncthreads();
    {
        const float lwj = __ldg(lw + j);
#pragma unroll
        for (int i = 0; i < APB; i++) hs[i][j] = siluf(acc[i]) * lwj;
    }
    __syncthreads();
    if (j < APB) {
        float s = __ldg(lb);
        for (int q = 0; q < 128; q++) s += hs[j][q];
        out[a0 + j] = s;
    }
}

extern "C" void kernel_launch(void* const* d_in, const int* in_sizes, int n_in,
                              void* d_out, int out_size)
{
    const float* pos     = (const float*)d_in[0];
    const float* cells   = (const float*)d_in[1];
    const int*   species = (const int*)d_in[2];
    const int*   shifts  = (const int*)d_in[3];
    const int*   ctr     = (const int*)d_in[4];
    const int*   nbr     = (const int*)d_in[5];
    const int*   spair   = (const int*)d_in[6];
    const float* embed   = (const float*)d_in[7];
    const float* rw1 = (const float*)d_in[8];
    const float* rb1 = (const float*)d_in[9];
    const float* rw2 = (const float*)d_in[10];
    const float* rb2 = (const float*)d_in[11];
    const float* ew1 = (const float*)d_in[12];
    const float* eb1 = (const float*)d_in[13];
    const float* ew2 = (const float*)d_in[14];
    const float* eb2 = (const float*)d_in[15];
    const float* mixa  = (const float*)d_in[16];
    const float* emixa = (const float*)d_in[17];
    const float* hw1 = (const float*)d_in[18];
    const float* hb1 = (const float*)d_in[19];
    const float* hw2 = (const float*)d_in[20];
    const float* hb2 = (const float*)d_in[21];
    const float* lw  = (const float*)d_in[22];
    const float* lb  = (const float*)d_in[23];
    const float* U2  = (const float*)d_in[24];
    float* out = (float*)d_out;

    zero_kernel<<<1024, 256>>>();
    hist_kernel<<<(NPAIRS + 255) / 256, 256>>>(ctr);
    scan_kernel<<<1, 1024>>>();
    scatter_kernel<<<(NPAIRS + 255) / 256, 256>>>(pos, cells, species, shifts, ctr, nbr, spair);
    pair_kernel<1><<<PAIR_BLOCKS, 128>>>(embed, rw1, rb1, rw2, rb2);
    cg_kernel<0><<<NATOMS, 128>>>(mixa, U2);
    pair_kernel<2><<<PAIR_BLOCKS, 128>>>(embed, ew1, eb1, ew2, eb2);
    cg_kernel<1><<<NATOMS, 128>>>(emixa, U2);
    head_kernel<<<NATOMS / APB, 128>>>(hw1, hb1, hw2, hb2, lw, lb, out);
}

// round 6
// speedup vs baseline: 1.3024x; 1.1140x over previous
#include <cuda_runtime.h>
#include <math.h>

#define NATOMS 5000
#define NPAIRS 160000
#define KCH 128
#define FEAT 1152               /* 9 * 128 */
#define MS 0.1767767f           /* MSG_SCALE */
#define ISC 0.2f                /* INIT_SCALE */
#define SQ3 1.7320508075688772f
#define NTILES (NPAIRS / 16)

__device__ float g_feats[NATOMS * FEAT];
__device__ float g_new[NATOMS * FEAT];
__device__ float4 g_rec[NPAIRS * 4];   /* sorted pair records, 64B each */
__device__ int g_cnt[NATOMS];
__device__ int g_off[NATOMS];

__device__ __forceinline__ float siluf(float x) { return x / (1.f + expf(-x)); }

typedef unsigned long long u64;
__device__ __forceinline__ u64 pk2(float lo, float hi) {
    u64 r; asm("mov.b64 %0,{%1,%2};" : "=l"(r) : "f"(lo), "f"(hi)); return r;
}
__device__ __forceinline__ void upk2(float& lo, float& hi, u64 v) {
    asm("mov.b64 {%0,%1},%2;" : "=f"(lo), "=f"(hi) : "l"(v));
}
__device__ __forceinline__ void fma2(u64& d, u64 a, u64 b) {
    asm("fma.rn.f32x2 %0,%1,%2,%0;" : "+l"(d) : "l"(a), "l"(b));
}

/* ---------------- zero feats + counters ---------------- */
__global__ void zero_kernel() {
    float4* p = (float4*)g_feats;
    const int n = NATOMS * FEAT / 4;
    const int tid = blockIdx.x * blockDim.x + threadIdx.x;
    for (int i = tid; i < n; i += gridDim.x * blockDim.x)
        p[i] = make_float4(0.f, 0.f, 0.f, 0.f);
    if (tid < NATOMS) g_cnt[tid] = 0;
}

/* ---------------- counting sort: hist / scan / scatter+geometry ------------ */
__global__ void hist_kernel(const int* __restrict__ ctr) {
    int p = blockIdx.x * blockDim.x + threadIdx.x;
    if (p < NPAIRS) atomicAdd(&g_cnt[__ldg(ctr + p)], 1);
}

__global__ __launch_bounds__(1024)
void scan_kernel() {
    __shared__ int wsum[32];
    const int t = threadIdx.x;
    const int base = t * 5;
    int c[5]; int s = 0;
#pragma unroll
    for (int i = 0; i < 5; i++) {
        int idx = base + i;
        c[i] = (idx < NATOMS) ? g_cnt[idx] : 0;
        s += c[i];
    }
    const int lane = t & 31, wid = t >> 5;
    int v = s;
#pragma unroll
    for (int o = 1; o < 32; o <<= 1) {
        int u = __shfl_up_sync(0xffffffffu, v, o);
        if (lane >= o) v += u;
    }
    if (lane == 31) wsum[wid] = v;
    __syncthreads();
    if (wid == 0) {
        int w = wsum[lane];
#pragma unroll
        for (int o = 1; o < 32; o <<= 1) {
            int u = __shfl_up_sync(0xffffffffu, w, o);
            if (lane >= o) w += u;
        }
        wsum[lane] = w;
    }
    __syncthreads();
    int excl = v - s + ((wid > 0) ? wsum[wid - 1] : 0);
#pragma unroll
    for (int i = 0; i < 5; i++) {
        int idx = base + i;
        if (idx < NATOMS) { g_off[idx] = excl; excl += c[i]; }
    }
}

__global__ void scatter_kernel(const float* __restrict__ pos, const float* __restrict__ cells,
                               const int* __restrict__ species, const int* __restrict__ shifts,
                               const int* __restrict__ ctr, const int* __restrict__ nbr,
                               const int* __restrict__ spair)
{
    const int p = blockIdx.x * blockDim.x + threadIdx.x;
    if (p >= NPAIRS) return;
    const int c = __ldg(ctr + p);
    const int n = __ldg(nbr + p);
    const int s = __ldg(spair + p);
    const float sx = (float)__ldg(shifts + 3 * p + 0) - 1.f;
    const float sy = (float)__ldg(shifts + 3 * p + 1) - 1.f;
    const float sz = (float)__ldg(shifts + 3 * p + 2) - 1.f;
    const float* M = cells + 9 * s;
    float vx = __ldg(pos + 3 * n + 0) - __ldg(pos + 3 * c + 0) + sx * __ldg(M + 0) + sy * __ldg(M + 3) + sz * __ldg(M + 6);
    float vy = __ldg(pos + 3 * n + 1) - __ldg(pos + 3 * c + 1) + sx * __ldg(M + 1) + sy * __ldg(M + 4) + sz * __ldg(M + 7);
    float vz = __ldg(pos + 3 * n + 2) - __ldg(pos + 3 * c + 2) + sx * __ldg(M + 2) + sy * __ldg(M + 5) + sz * __ldg(M + 8);
    const float dd = vx * vx + vy * vy + vz * vz + 1e-12f;
    const float d = sqrtf(dd);
    const float id = 1.f / d;
    const float fc = (d < 5.f) ? 0.5f * (cosf(0.6283185307179586f * d) + 1.f) : 0.f;
    float in[8];
#pragma unroll
    for (int b = 0; b < 8; b++) {
        float t = d - 0.7142857142857143f * (float)b;
        in[b] = expf(-2.f * t * t) * fc;
    }
    const int dst = atomicAdd(&g_off[c], 1);
    float4* r = g_rec + dst * 4;
    r[0] = make_float4(__int_as_float(c), __int_as_float(n), __int_as_float(__ldg(species + n)), d);
    r[1] = make_float4(vx * id, vy * id, vz * id, 0.f);
    r[2] = make_float4(in[0], in[1], in[2], in[3]);
    r[3] = make_float4(in[4], in[5], in[6], in[7]);
}

/* ---------------- pair kernels: block-cooperative 16-pair tiles ------------
 * warp w owns channels k = 32w + lane (R rows {w, w+4, w+8}).
 * Hidden h for the warp's 4 pairs is published to smem packed; after barrier
 * each warp GEMMs all 16 pairs for its 3 rows. Epilogue merges per-center in
 * 9 registers, flushing with atomics on center change.
 */
template <int PASS>
__global__ __launch_bounds__(128, 4)
void pair_kernel(const float* __restrict__ embed,
                 const float* __restrict__ w1, const float* __restrict__ b1,
                 const float* __restrict__ w2, const float* __restrict__ b2)
{
    __shared__ float w2s[12288];
    __shared__ float w1s[256];
    __shared__ float b1s[32];
    __shared__ float b2s[384];
    __shared__ u64 hs[256];        /* [pairpair 0..7][unit b 0..31] */
    {
        float4* d4 = (float4*)w2s;
        const float4* s4 = (const float4*)w2;
        for (int i = threadIdx.x; i < 3072; i += 128) d4[i] = s4[i];
        for (int i = threadIdx.x; i < 256; i += 128) w1s[i] = w1[i];
        if (threadIdx.x < 32) b1s[threadIdx.x] = b1[threadIdx.x];
        for (int i = threadIdx.x; i < 384; i += 128) b2s[i] = b2[i];
    }
    __syncthreads();

    const int lane = threadIdx.x & 31;
    const int w = threadIdx.x >> 5;
    const int kb = w * 32 + lane;      /* channel owned by this thread */

    const u64 bi0 = pk2(b2s[kb], b2s[kb]);
    const u64 bi1 = pk2(b2s[128 + kb], b2s[128 + kb]);
    const u64 bi2 = pk2(b2s[256 + kb], b2s[256 + kb]);

    float accE[9];
#pragma unroll
    for (int i = 0; i < 9; i++) accE[i] = 0.f;
    int cur_c = -1;

#define FLUSHE()                                                                \
    do {                                                                        \
        float* fb = ((PASS == 1) ? g_feats : g_new) + cur_c * FEAT + kb;        \
        _Pragma("unroll")                                                       \
        for (int comp = 0; comp < 9; comp++)                                    \
            atomicAdd(fb + comp * KCH, accE[comp]);                             \
    } while (0)

    for (int tile = blockIdx.x; tile < NTILES; tile += gridDim.x) {
        const int q0 = tile * 16;

        /* hidden layer: warp w handles pairs q0+4w .. q0+4w+3 */
        float hac[4];
#pragma unroll
        for (int pp = 0; pp < 4; pp++) {
            const float4* r = g_rec + (q0 + 4 * w + pp) * 4;
            const float4 i0 = __ldg(r + 2);
            const float4 i1 = __ldg(r + 3);
            float h = b1s[lane]
                + i0.x * w1s[lane]        + i0.y * w1s[32 + lane]
                + i0.z * w1s[64 + lane]   + i0.w * w1s[96 + lane]
                + i1.x * w1s[128 + lane]  + i1.y * w1s[160 + lane]
                + i1.z * w1s[192 + lane]  + i1.w * w1s[224 + lane];
            hac[pp] = siluf(h);
        }
        hs[(2 * w + 0) * 32 + lane] = pk2(hac[0], hac[1]);
        hs[(2 * w + 1) * 32 + lane] = pk2(hac[2], hac[3]);
        __syncthreads();

        /* GEMM: 16 pairs (8 packed) x 3 rows for this warp's channels */
        u64 A0[8], A1[8], A2[8];
#pragma unroll
        for (int j = 0; j < 8; j++) { A0[j] = bi0; A1[j] = bi1; A2[j] = bi2; }
#pragma unroll 8
        for (int b = 0; b < 32; b++) {
            const float w0f = w2s[b * 384 + kb];
            const float w1f = w2s[b * 384 + 128 + kb];
            const float w2f = w2s[b * 384 + 256 + kb];
            const u64 wv0 = pk2(w0f, w0f);
            const u64 wv1 = pk2(w1f, w1f);
            const u64 wv2 = pk2(w2f, w2f);
#pragma unroll
            for (int j = 0; j < 8; j++) {
                const u64 hb = hs[j * 32 + b];
                fma2(A0[j], wv0, hb);
                fma2(A1[j], wv1, hb);
                fma2(A2[j], wv2, hb);
            }
        }

        /* epilogue: all 16 pairs, this warp's channel subset */
#pragma unroll
        for (int j = 0; j < 8; j++) {
            float r0v[2], r1v[2], r2v[2];
            upk2(r0v[0], r0v[1], A0[j]);
            upk2(r1v[0], r1v[1], A1[j]);
            upk2(r2v[0], r2v[1], A2[j]);
#pragma unroll
            for (int e = 0; e < 2; e++) {
                const int p = q0 + 2 * j + e;
                const float4* r = g_rec + p * 4;
                const float4 a0 = __ldg(r + 0);
                const float4 uu = __ldg(r + 1);
                const int c = __float_as_int(a0.x);
                const int n = __float_as_int(a0.y);
                const int sp = __float_as_int(a0.z);
                const float x = uu.x, y = uu.y, z = uu.z;

                if (c != cur_c) {
                    if (cur_c >= 0) FLUSHE();
                    cur_c = c;
#pragma unroll
                    for (int i = 0; i < 9; i++) accE[i] = 0.f;
                }

                const float sh1 = ISC * y, sh2 = ISC * z, sh3 = ISC * x;
                const float sh4 = ISC * SQ3 * x * y;
                const float sh5 = ISC * SQ3 * y * z;
                const float sh6 = ISC * 0.5f * (3.f * z * z - 1.f);
                const float sh7 = ISC * SQ3 * x * z;
                const float sh8 = ISC * 0.5f * SQ3 * (x * x - y * y);

                if (PASS == 1) {
                    const float e_ = __ldg(embed + sp * KCH + kb) * MS;
                    const float r0 = r0v[e] * e_, r1 = r1v[e] * e_, r2 = r2v[e] * e_;
                    accE[0] += ISC * r0;
                    accE[1] += sh1 * r1;
                    accE[2] += sh2 * r1;
                    accE[3] += sh3 * r1;
                    accE[4] += sh4 * r2;
                    accE[5] += sh5 * r2;
                    accE[6] += sh6 * r2;
                    accE[7] += sh7 * r2;
                    accE[8] += sh8 * r2;
                } else {
                    const float r0 = r0v[e] * MS, r1 = r1v[e] * MS, r2 = r2v[e] * MS;
                    const float* gn = g_feats + n * FEAT;
                    const float inv = __ldg(gn + kb);
                    const float u1 = r1 * inv, u2 = r2 * inv;
                    accE[0] += ISC * r0 * inv + r0 * inv;
                    accE[1] += sh1 * u1 + r0 * __ldg(gn + 1 * KCH + kb);
                    accE[2] += sh2 * u1 + r0 * __ldg(gn + 2 * KCH + kb);
                    accE[3] += sh3 * u1 + r0 * __ldg(gn + 3 * KCH + kb);
                    accE[4] += sh4 * u2 + r0 * __ldg(gn + 4 * KCH + kb);
                    accE[5] += sh5 * u2 + r0 * __ldg(gn + 5 * KCH + kb);
                    accE[6] += sh6 * u2 + r0 * __ldg(gn + 6 * KCH + kb);
                    accE[7] += sh7 * u2 + r0 * __ldg(gn + 7 * KCH + kb);
                    accE[8] += sh8 * u2 + r0 * __ldg(gn + 8 * KCH + kb);
                }
            }
        }
        __syncthreads();   /* protect hs before next tile's stores */
    }
    if (cur_c >= 0) FLUSHE();
#undef FLUSHE
}

/* ---------------- CG tensor-square iterate (per atom, per k) ---------------- */
template <int BUF>
__global__ __launch_bounds__(128)
void cg_kernel(const float* __restrict__ mix, const float* __restrict__ U2g)
{
    __shared__ float U[81];
    const int k = threadIdx.x;
    if (k < 81) U[k] = U2g[k];
    __syncthreads();
    float* base = ((BUF == 0) ? g_feats : g_new) + blockIdx.x * FEAT + k;
    float* dup  = g_new + blockIdx.x * FEAT + k;

    {
        const float f0 = base[0];
        const float v = f0 + __ldg(mix + k) * f0 * f0;
        base[0] = v;
        if (BUF == 0) dup[0] = v;
    }
    {
        float f1[3];
#pragma unroll
        for (int j = 0; j < 3; j++) f1[j] = base[(1 + j) * KCH];
        float Mv[9];
#pragma unroll
        for (int q = 0; q < 9; q++)
            Mv[q] = U[9 + q] * f1[0] + U[18 + q] * f1[1] + U[27 + q] * f1[2];
        float Cm[9];
#pragma unroll
        for (int i = 0; i < 3; i++)
#pragma unroll
            for (int j = 0; j < 3; j++)
                Cm[3 * i + j] = Mv[3 * i] * Mv[j] + Mv[3 * i + 1] * Mv[3 + j] + Mv[3 * i + 2] * Mv[6 + j];
        const float m1 = __ldg(mix + KCH + k);
        float B[9];
#pragma unroll
        for (int q = 0; q < 9; q++) B[q] = Mv[q] + m1 * Cm[q];
#pragma unroll
        for (int j = 0; j < 3; j++) {
            float o = 0.f;
#pragma unroll
            for (int q = 0; q < 9; q++) o += U[(1 + j) * 9 + q] * B[q];
            base[(1 + j) * KCH] = o;
            if (BUF == 0) dup[(1 + j) * KCH] = o;
        }
    }
    {
        float f2[5];
#pragma unroll
        for (int j = 0; j < 5; j++) f2[j] = base[(4 + j) * KCH];
        float Mv[9];
#pragma unroll
        for (int q = 0; q < 9; q++)
            Mv[q] = U[36 + q] * f2[0] + U[45 + q] * f2[1] + U[54 + q] * f2[2] + U[63 + q] * f2[3] + U[72 + q] * f2[4];
        float Cm[9];
#pragma unroll
        for (int i = 0; i < 3; i++)
#pragma unroll
            for (int j = 0; j < 3; j++)
                Cm[3 * i + j] = Mv[3 * i] * Mv[j] + Mv[3 * i + 1] * Mv[3 + j] + Mv[3 * i + 2] * Mv[6 + j];
        const float m2 = __ldg(mix + 2 * KCH + k);
        float B[9];
#pragma unroll
        for (int q = 0; q < 9; q++) B[q] = Mv[q] + m2 * Cm[q];
#pragma unroll
        for (int j = 0; j < 5; j++) {
            float o = 0.f;
#pragma unroll
            for (int q = 0; q < 9; q++) o += U[(4 + j) * 9 + q] * B[q];
            base[(4 + j) * KCH] = o;
            if (BUF == 0) dup[(4 + j) * KCH] = o;
        }
    }
}

/* ---------------- head MLP: 20 atoms per block ---------------- */
#define APB 20
__global__ __launch_bounds__(128)
void head_kernel(const float* __restrict__ hw1, const float* __restrict__ hb1,
                 const float* __restrict__ hw2, const float* __restrict__ hb2,
                 const float* __restrict__ lw, const float* __restrict__ lb,
                 float* __restrict__ out)
{
    __shared__ float hs[APB][132];
    const int a0 = blockIdx.x * APB;
    const int j = threadIdx.x;

    for (int i = 0; i < APB; i++) hs[i][j] = g_new[(a0 + i) * FEAT + j];
    __syncthreads();

    float acc[APB];
    {
        const float b = __ldg(hb1 + j);
#pragma unroll
        for (int i = 0; i < APB; i++) acc[i] = b;
    }
    for (int kk = 0; kk < 128; kk++) {
        const float w = __ldg(hw1 + kk * 128 + j);
#pragma unroll
        for (int i = 0; i < APB; i++) acc[i] += hs[i][kk] * w;
    }
    __syncthreads();
#pragma unroll
    for (int i = 0; i < APB; i++) hs[i][j] = siluf(acc[i]);
    __syncthreads();
    {
        const float b = __ldg(hb2 + j);
#pragma unroll
        for (int i = 0; i < APB; i++) acc[i] = b;
    }
    for (int kk = 0; kk < 128; kk++) {
        const float w = __ldg(hw2 + kk * 128 + j);
#pragma unroll
        for (int i = 0; i < APB; i++) acc[i] += hs[i][kk] * w;
    }
    __syncthreads();
    {
        const float lwj = __ldg(lw + j);
#pragma unroll
        for (int i = 0; i < APB; i++) hs[i][j] = siluf(acc[i]) * lwj;
    }
    __syncthreads();
    if (j < APB) {
        float s = __ldg(lb);
        for (int q = 0; q < 128; q++) s += hs[j][q];
        out[a0 + j] = s;
    }
}

extern "C" void kernel_launch(void* const* d_in, const int* in_sizes, int n_in,
                              void* d_out, int out_size)
{
    const float* pos     = (const float*)d_in[0];
    const float* cells   = (const float*)d_in[1];
    const int*   species = (const int*)d_in[2];
    const int*   shifts  = (const int*)d_in[3];
    const int*   ctr     = (const int*)d_in[4];
    const int*   nbr     = (const int*)d_in[5];
    const int*   spair   = (const int*)d_in[6];
    const float* embed   = (const float*)d_in[7];
    const float* rw1 = (const float*)d_in[8];
    const float* rb1 = (const float*)d_in[9];
    const float* rw2 = (const float*)d_in[10];
    const float* rb2 = (const float*)d_in[11];
    const float* ew1 = (const float*)d_in[12];
    const float* eb1 = (const float*)d_in[13];
    const float* ew2 = (const float*)d_in[14];
    const float* eb2 = (const float*)d_in[15];
    const float* mixa  = (const float*)d_in[16];
    const float* emixa = (const float*)d_in[17];
    const float* hw1 = (const float*)d_in[18];
    const float* hb1 = (const float*)d_in[19];
    const float* hw2 = (const float*)d_in[20];
    const float* hb2 = (const float*)d_in[21];
    const float* lw  = (const float*)d_in[22];
    const float* lb  = (const float*)d_in[23];
    const float* U2  = (const float*)d_in[24];
    float* out = (float*)d_out;

    zero_kernel<<<1024, 256>>>();
    hist_kernel<<<(NPAIRS + 255) / 256, 256>>>(ctr);
    scan_kernel<<<1, 1024>>>();
    scatter_kernel<<<(NPAIRS + 255) / 256, 256>>>(pos, cells, species, shifts, ctr, nbr, spair);
    pair_kernel<1><<<592, 128>>>(embed, rw1, rb1, rw2, rb2);
    cg_kernel<0><<<NATOMS, 128>>>(mixa, U2);
    pair_kernel<2><<<592, 128>>>(embed, ew1, eb1, ew2, eb2);
    cg_kernel<1><<<NATOMS, 128>>>(emixa, U2);
    head_kernel<<<NATOMS / APB, 128>>>(hw1, hb1, hw2, hb2, lw, lb, out);
}